// round 11
// baseline (speedup 1.0000x reference)
#include <cuda_runtime.h>
#include <cstdint>

#define NTOK 4096
#define DIM  1024
#define HDIM 4096
#define NE   8

#define TM 128
#define TN 128
#define TK 16
#define PAD 132   // smem row stride in floats (528B, 16B-aligned, %32 != 0)

__device__ int   g_counts[NE];
__device__ int   g_tlist[NE * NTOK];
__device__ float g_h[(size_t)NTOK * HDIM];   // relu(x@fc)^2 scratch, 64 MB (<= proven-safe budget)

typedef unsigned long long ull;

__device__ __forceinline__ ull pack2(float x, float y) {
    ull r;
    asm("mov.b64 %0, {%1,%2};" : "=l"(r) : "f"(x), "f"(y));
    return r;
}
__device__ __forceinline__ void fma2(ull& d, ull a, ull b) {
    asm("fma.rn.f32x2 %0, %1, %2, %0;" : "+l"(d) : "l"(a), "l"(b));
}
__device__ __forceinline__ float2 unpack2(ull v) {
    float2 f;
    asm("mov.b64 {%0,%1}, %2;" : "=f"(f.x), "=f"(f.y) : "l"(v));
    return f;
}

// ---------------------------------------------------------------------------
__global__ void init_counts_kernel() {
    if (threadIdx.x < NE) g_counts[threadIdx.x] = 0;
}

__global__ void router_kernel(const float* __restrict__ x,
                              const float* __restrict__ rw) {
    int warp = (blockIdx.x * blockDim.x + threadIdx.x) >> 5;
    int lane = threadIdx.x & 31;
    if (warp >= NTOK) return;
    const float* xr = x + (size_t)warp * DIM;
    float best = -1e30f;
    int bestE = 0;
#pragma unroll
    for (int e = 0; e < NE; e++) {
        const float* wr = rw + e * DIM;
        float p = 0.f;
        for (int k = lane; k < DIM; k += 32) p += xr[k] * wr[k];
#pragma unroll
        for (int o = 16; o; o >>= 1) p += __shfl_xor_sync(0xffffffffu, p, o);
        if (p > best) { best = p; bestE = e; }   // strict > => first-max (jnp.argmax)
    }
    if (lane == 0) {
        int slot = atomicAdd(&g_counts[bestE], 1);
        g_tlist[bestE * NTOK + slot] = warp;
    }
}

// ---------------------------------------------------------------------------
// Gathered grouped fp32 GEMM via packed fma.rn.f32x2.
// Tile 128x128, 256 threads, 8x8 outputs/thread in split quads:
//   cols tx*4..+3 and 64+tx*4..+3 ; rows ty*4..+3 and 64+ty*4..+3.
// smem: As[k][m], Bs[k][n], stride PAD floats.
// BTRANS=true : B elem (k,n) at Bq[k*HDIM+n]  (GEMM1, fc)   -> direct row copy
// BTRANS=false: B elem (n,k) at Bq[n*HDIM+k]  (GEMM2, proj) -> transpose on store (R1 mapping)
template <int KTOT, bool RELU2, bool BTRANS>
__global__ __launch_bounds__(256, 2) void gemm_f32x2(
    const float* __restrict__ Abase, int astride,
    const float* __restrict__ Bbase,
    float* __restrict__ Obase, int ostride)
{
    constexpr int KT = KTOT / TK;

    __shared__ int   toks[TM];
    __shared__ float As[2][TK][PAD];
    __shared__ float Bs[2][TK][PAD];

    const int e = blockIdx.z;
    const int count = g_counts[e];
    const int m0 = blockIdx.y * TM;
    if (m0 >= count) return;
    const int n0 = blockIdx.x * TN;

    const int tid = threadIdx.x;
    if (tid < TM) {
        int mg = m0 + tid;
        toks[tid] = (mg < count) ? g_tlist[e * NTOK + mg] : -1;
    }
    __syncthreads();

    const float* Bq = Bbase + (size_t)e * DIM * HDIM;

    // ---- load-slot mappings (2 slots of 256 threads each; R1-style) ----
    // A: 128 rows x 16 k -> 512 float4; idx = q*256+tid; row=idx>>2, kq=(idx&3)*4
    const float* aptr[2];
    int arow[2], akq[2];
#pragma unroll
    for (int q = 0; q < 2; q++) {
        int idx = q * 256 + tid;
        arow[q] = idx >> 2;
        akq[q]  = (idx & 3) * 4;
        int tok = toks[arow[q]];
        aptr[q] = (tok >= 0) ? (Abase + (size_t)tok * astride + akq[q]) : nullptr;
    }
    const float* bptr[2];
    int brow[2], bkq[2], bkk[2], bn4[2];
#pragma unroll
    for (int q = 0; q < 2; q++) {
        int idx = q * 256 + tid;
        if (BTRANS) {                       // tile [k=16][n=128]
            bkk[q] = idx >> 5;              // 0..15
            bn4[q] = (idx & 31) * 4;        // 0..124
            bptr[q] = Bq + (size_t)bkk[q] * HDIM + n0 + bn4[q];
        } else {                            // src [n][k] -> transpose on store
            brow[q] = idx >> 2;             // n: 0..127
            bkq[q]  = (idx & 3) * 4;        // k: 0,4,8,12
            bptr[q] = Bq + (size_t)(n0 + brow[q]) * HDIM + bkq[q];
        }
    }

    float4 ra[2], rb[2];
    auto LOAD = [&](int k0) {
#pragma unroll
        for (int q = 0; q < 2; q++) {
            ra[q] = aptr[q] ? *(const float4*)(aptr[q] + k0)
                            : make_float4(0.f, 0.f, 0.f, 0.f);
            if (BTRANS) rb[q] = *(const float4*)(bptr[q] + (size_t)k0 * HDIM);
            else        rb[q] = *(const float4*)(bptr[q] + k0);
        }
    };
    auto STORE = [&](int s) {
#pragma unroll
        for (int q = 0; q < 2; q++) {
            As[s][akq[q] + 0][arow[q]] = ra[q].x;   // transpose (R1-proven)
            As[s][akq[q] + 1][arow[q]] = ra[q].y;
            As[s][akq[q] + 2][arow[q]] = ra[q].z;
            As[s][akq[q] + 3][arow[q]] = ra[q].w;
            if (BTRANS) {
                *(float4*)&Bs[s][bkk[q]][bn4[q]] = rb[q];
            } else {
                Bs[s][bkq[q] + 0][brow[q]] = rb[q].x;
                Bs[s][bkq[q] + 1][brow[q]] = rb[q].y;
                Bs[s][bkq[q] + 2][brow[q]] = rb[q].z;
                Bs[s][bkq[q] + 3][brow[q]] = rb[q].w;
            }
        }
    };

    const int tx4 = (tid & 15) * 4;        // col quads at tx4 and 64+tx4
    const int ty4 = (tid >> 4) * 4;        // row quads at ty4 and 64+ty4

    ull acc[8][4];
#pragma unroll
    for (int i = 0; i < 8; i++)
#pragma unroll
        for (int j = 0; j < 4; j++) acc[i][j] = 0ull;

    LOAD(0);
    STORE(0);
    __syncthreads();

    for (int kt = 0; kt < KT; kt++) {
        const int s = kt & 1;
        if (kt + 1 < KT) LOAD((kt + 1) * TK);

#pragma unroll
        for (int kk = 0; kk < TK; kk++) {
            // A: half-warp broadcast (lanes 0-15 same ty) — conflict-free
            float4 a0 = *(const float4*)&As[s][kk][ty4];
            float4 a1 = *(const float4*)&As[s][kk][64 + ty4];
            // B: lanes 0-15 read 16 consecutive 16B chunks — conflict-free
            ulonglong2 bq0 = *(const ulonglong2*)&Bs[s][kk][tx4];
            ulonglong2 bq1 = *(const ulonglong2*)&Bs[s][kk][64 + tx4];
            ull b[4] = {bq0.x, bq0.y, bq1.x, bq1.y};
            ull ap[8] = {pack2(a0.x, a0.x), pack2(a0.y, a0.y),
                         pack2(a0.z, a0.z), pack2(a0.w, a0.w),
                         pack2(a1.x, a1.x), pack2(a1.y, a1.y),
                         pack2(a1.z, a1.z), pack2(a1.w, a1.w)};
#pragma unroll
            for (int i = 0; i < 8; i++)
#pragma unroll
                for (int j = 0; j < 4; j++) fma2(acc[i][j], ap[i], b[j]);
        }

        if (kt + 1 < KT) {
            __syncthreads();
            STORE(s ^ 1);
            __syncthreads();
        }
    }

    // ---- epilogue: 8 rows x (two separated col quads) ----
#pragma unroll
    for (int i = 0; i < 8; i++) {
        int row = (i < 4) ? (ty4 + i) : (64 + ty4 + i - 4);
        int tok = toks[row];
        if (tok < 0) continue;
        float2 p0 = unpack2(acc[i][0]);
        float2 p1 = unpack2(acc[i][1]);
        float2 p2 = unpack2(acc[i][2]);
        float2 p3 = unpack2(acc[i][3]);
        if (RELU2) {
            p0.x = fmaxf(p0.x, 0.f); p0.x *= p0.x;
            p0.y = fmaxf(p0.y, 0.f); p0.y *= p0.y;
            p1.x = fmaxf(p1.x, 0.f); p1.x *= p1.x;
            p1.y = fmaxf(p1.y, 0.f); p1.y *= p1.y;
            p2.x = fmaxf(p2.x, 0.f); p2.x *= p2.x;
            p2.y = fmaxf(p2.y, 0.f); p2.y *= p2.y;
            p3.x = fmaxf(p3.x, 0.f); p3.x *= p3.x;
            p3.y = fmaxf(p3.y, 0.f); p3.y *= p3.y;
        }
        float* o = Obase + (size_t)tok * ostride + n0;
        *(float4*)(o + tx4)      = make_float4(p0.x, p0.y, p1.x, p1.y);
        *(float4*)(o + 64 + tx4) = make_float4(p2.x, p2.y, p3.x, p3.y);
    }
}

// ---------------------------------------------------------------------------
extern "C" void kernel_launch(void* const* d_in, const int* in_sizes, int n_in,
                              void* d_out, int out_size) {
    const float* x    = (const float*)d_in[0];
    const float* rw   = (const float*)d_in[1];
    const float* fc   = (const float*)d_in[2];
    const float* proj = (const float*)d_in[3];
    float* out = (float*)d_out;

    init_counts_kernel<<<1, 32>>>();
    router_kernel<<<(NTOK * 32) / 256, 256>>>(x, rw);

    dim3 g1(HDIM / TN, NTOK / TM, NE);   // 32 x 32 x 8, most blocks early-exit
    gemm_f32x2<DIM, true, true><<<g1, 256>>>(x, DIM, fc, g_h, HDIM);

    dim3 g2(DIM / TN, NTOK / TM, NE);    // 8 x 32 x 8
    gemm_f32x2<HDIM, false, false><<<g2, 256>>>(g_h, HDIM, proj, out, DIM);
}